// round 4
// baseline (speedup 1.0000x reference)
#include <cuda_runtime.h>
#include <math.h>

#define BS   8
#define T_   32
#define C_   64
#define NN   4096
#define KK   32
#define DD   64
#define HH   64
#define FIN  320   // 5*D

// ---------------- persistent scratch (no allocation allowed) ----------------
__device__ float g_pm[2][BS * NN * DD];   // double-buffered messages
__device__ float g_h [BS * NN * DD];      // hidden state (in-place per update)
__device__ float g_ep[BS * NN * DD];      // eff_prim
__device__ float g_ek[BS * NN * DD];      // eff_key
__device__ float g_ed[BS * NN];           // eff_decay (scalar per b,n)

// fast sigmoid: RCP-based division, err ~2ulp
__device__ __forceinline__ float sigf(float x) {
    return __fdividef(1.f, 1.f + __expf(-x));
}
// fast tanh: 1 - 2/(e^{2x}+1).  ~6 instr / 2 MUFU, rel err ~1e-6.
// Saturates correctly: x->+inf => e=inf => 1; x->-inf => e=0 => -1.
__device__ __forceinline__ float tanhfast(float x) {
    const float e = __expf(2.f * x);
    return 1.f - __fdividef(2.f, e + 1.f);
}

// =============================================================================
// Kernel A: modulator MLP + state init.  One CTA per neuron n, 512 threads.
// =============================================================================
__global__ void __launch_bounds__(512) modk(
    const float* __restrict__ h_in, const float* __restrict__ pm_in,
    const float* __restrict__ tp,   const float* __restrict__ tk,
    const float* __restrict__ prim, const float* __restrict__ keyp,
    const float* __restrict__ dlog, const float* __restrict__ fc1w,
    const float* __restrict__ fc1b, const float* __restrict__ fc2w,
    const float* __restrict__ fc2b, const float* __restrict__ mll)
{
    const int n   = blockIdx.x;
    const int tid = threadIdx.x;

    __shared__ __align__(16) float s_in[FIN * 12];      // [j][b] pad 12 (float4-friendly)
    __shared__ float s_part[8 * 8 * 64];                // [seg][b][h]
    __shared__ float s_x[8 * 64];                       // tanh(fc1) activations
    __shared__ float s_o[24];                           // fc2 outputs [b][3]
    __shared__ float s_norm[16];                        // [b][{prim,key}]

    // ---- stage mod_input transposed: s_in[j*12 + b] ----
    for (int idx = tid; idx < BS * FIN; idx += 512) {
        const int b = idx / FIN, j = idx % FIN;
        float v;
        if      (j <  64) v = h_in[((size_t)b * NN + n) * DD + j];
        else if (j < 128) v = tp  [((size_t)b * NN + n) * DD + j - 64];
        else if (j < 192) v = tk  [((size_t)b * NN + n) * DD + j - 128];
        else if (j < 256) v = prim[(size_t)n * DD + j - 192];
        else              v = keyp[(size_t)n * DD + j - 256];
        s_in[j * 12 + b] = v;
    }
    __syncthreads();

    // ---- fc1: thread (seg,h) covers j in [seg*40, seg*40+40) for ALL 8 batches ----
    {
        const int seg = tid >> 6, hh = tid & 63;
        float a0=0,a1=0,a2=0,a3=0,a4=0,a5=0,a6=0,a7=0;
        const float* W = fc1w + (size_t)n * FIN * HH + hh;
        const int j0 = seg * 40;
        #pragma unroll 8
        for (int jj = 0; jj < 40; jj++) {
            const int j = j0 + jj;
            const float w = W[(size_t)j * HH];
            const float4 i0 = *(const float4*)&s_in[j * 12];
            const float4 i1 = *(const float4*)&s_in[j * 12 + 4];
            a0 += w * i0.x; a1 += w * i0.y; a2 += w * i0.z; a3 += w * i0.w;
            a4 += w * i1.x; a5 += w * i1.y; a6 += w * i1.z; a7 += w * i1.w;
        }
        float acc[8] = {a0,a1,a2,a3,a4,a5,a6,a7};
        #pragma unroll
        for (int b = 0; b < 8; b++)
            s_part[(seg * 8 + b) * 64 + hh] = acc[b];
    }
    __syncthreads();

    // ---- reduce segments, bias, tanh ----
    {
        const int b = tid >> 6, h = tid & 63;
        float s = 0.f;
        #pragma unroll
        for (int seg = 0; seg < 8; seg++) s += s_part[(seg * 8 + b) * 64 + h];
        s_x[b * 64 + h] = tanhfast(s + fc1b[(size_t)n * HH + h]);
    }
    __syncthreads();

    // ---- fc2 (24 threads) + trace norms (threads 32..47) ----
    if (tid < 24) {
        const int b = tid / 3, o = tid % 3;
        float acc = fc2b[(size_t)n * 3 + o];
        #pragma unroll 8
        for (int h = 0; h < 64; h++)
            acc += s_x[b * 64 + h] * fc2w[((size_t)n * 64 + h) * 3 + o];
        s_o[b * 3 + o] = acc;
    } else if (tid >= 32 && tid < 48) {
        const int q = tid - 32, b = q >> 1, which = q & 1;
        float s = 0.f;
        const int base = 64 + which * 64;
        #pragma unroll 8
        for (int d = 0; d < 64; d++) {
            const float v = s_in[(base + d) * 12 + b];
            s += v * v;
        }
        s_norm[b * 2 + which] = fmaxf(sqrtf(s), 1e-8f);
    }
    __syncthreads();

    // ---- finalize eff_* and init state ----
    {
        const int b = tid >> 6, d = tid & 63;
        const float mod_lr = sigf(mll[0]);
        const float gp = tanhfast(s_o[b * 3 + 0]);
        const float gk = tanhfast(s_o[b * 3 + 1]);
        const float dm = s_o[b * 3 + 2];
        const float tpv = s_in[(64 + d) * 12 + b];
        const float tkv = s_in[(128 + d) * 12 + b];
        const size_t off = ((size_t)b * NN + n) * DD + d;
        g_ep[off] = prim[(size_t)n * DD + d] + mod_lr * gp * (tpv / s_norm[b * 2 + 0]);
        g_ek[off] = keyp[(size_t)n * DD + d] + mod_lr * gk * (tkv / s_norm[b * 2 + 1]);
        g_h [off] = s_in[d * 12 + b];
        g_pm[0][off] = pm_in[off];
        if (d == 0) g_ed[(size_t)b * NN + n] = sigf(dlog[n] + dm);
    }
}

// =============================================================================
// Kernel B: one scan update.  One CTA per neuron n, 8 warps = 8 batches.
// Messages live entirely in registers (lane l owns d=2l,2l+1); sims via a
// 5-stage butterfly multi-reduce (8 sims per chunk).  smem = 9.3 KB static.
// =============================================================================
__global__ void __launch_bounds__(256, 5) stepk(
    int parity, int t0,
    const float* __restrict__ cc, const float* __restrict__ bw,
    const float* __restrict__ gw, const int* __restrict__ conn,
    float* __restrict__ out)
{
    __shared__ float s_bw[2048];   // [k][d]
    __shared__ float s_gw[256];    // [nb][d]
    __shared__ int   s_idx[32];

    const int n   = blockIdx.x;
    const int tid = threadIdx.x;
    const int b   = tid >> 5;
    const int l   = tid & 31;

    const float* pm_in  = g_pm[parity];
    float*       pm_out = g_pm[parity ^ 1];

    #pragma unroll
    for (int i = 0; i < 8; i++) s_bw[tid + 256 * i] = bw[(size_t)n * 2048 + tid + 256 * i];
    s_gw[tid] = gw[(size_t)n * 256 + tid];
    if (tid < 32) s_idx[tid] = conn[(size_t)n * KK + tid];

    const size_t off = ((size_t)b * NN + n) * DD;
    const float2 key = *(const float2*)&g_ek[off + 2 * l];
    __syncthreads();

    const float* pmb = pm_in + (size_t)b * NN * DD;
    float2 accv[4];

    #pragma unroll
    for (int c = 0; c < 4; c++) {
        // ---- gather 8 messages: lane l holds d=2l, 2l+1 of each ----
        float2 m[8];
        #pragma unroll
        for (int kk = 0; kk < 8; kk++) {
            const int src = s_idx[c * 8 + kk];
            m[kk] = __ldg((const float2*)&pmb[src * DD + 2 * l]);
        }

        // ---- per-lane sim partials ----
        float v[8];
        #pragma unroll
        for (int kk = 0; kk < 8; kk++)
            v[kk] = key.x * m[kk].x + key.y * m[kk].y;

        // ---- butterfly multi-reduce: 8 sums over 32 lanes in 5 stages ----
        {
            const bool h16 = (l & 16);
            #pragma unroll
            for (int i = 0; i < 4; i++) {
                const float keep = h16 ? v[4 + i] : v[i];
                const float send = h16 ? v[i]     : v[4 + i];
                v[i] = keep + __shfl_xor_sync(0xffffffffu, send, 16);
            }
            const bool h8 = (l & 8);
            #pragma unroll
            for (int i = 0; i < 2; i++) {
                const float keep = h8 ? v[2 + i] : v[i];
                const float send = h8 ? v[i]     : v[2 + i];
                v[i] = keep + __shfl_xor_sync(0xffffffffu, send, 8);
            }
            const bool h4 = (l & 4);
            {
                const float keep = h4 ? v[1] : v[0];
                const float send = h4 ? v[0] : v[1];
                v[0] = keep + __shfl_xor_sync(0xffffffffu, send, 4);
            }
            v[0] += __shfl_xor_sync(0xffffffffu, v[0], 2);
            v[0] += __shfl_xor_sync(0xffffffffu, v[0], 1);
        }
        // lane l now holds sim for kk = (l >> 2) & 7
        const float w = sigf(v[0]);

        // ---- weighted + branch partial sums ----
        float ax = 0.f, ay = 0.f;
        #pragma unroll
        for (int kk = 0; kk < 8; kk++) {
            const float wk = __shfl_sync(0xffffffffu, w, kk << 2);
            const float2 bwv = *(const float2*)&s_bw[(c * 8 + kk) * 64 + 2 * l];
            ax += (wk * m[kk].x) * bwv.x;
            ay += (wk * m[kk].y) * bwv.y;
        }
        accv[c].x = ax; accv[c].y = ay;
    }

    // ---- branch tanh -> group sum -> group tanh (ng=1, mean = identity) ----
    float r0 = 0.f, r1 = 0.f;
    #pragma unroll
    for (int nb = 0; nb < 4; nb++) {
        const float2 gwv = *(const float2*)&s_gw[nb * 64 + 2 * l];
        r0 += tanhfast(accv[nb].x) * gwv.x;
        r1 += tanhfast(accv[nb].y) * gwv.y;
    }
    r0 = tanhfast(r0);
    r1 = tanhfast(r1);

    if (n < C_) {   // cc injection on first C neurons
        const float2 ccv = *(const float2*)&cc[(((size_t)b * T_ + t0) * C_ + n) * DD + 2 * l];
        r0 += ccv.x;
        r1 += ccv.y;
    }

    // ---- h / message update ----
    const float ed = g_ed[(size_t)b * NN + n];
    const float2 h = *(const float2*)&g_h[off + 2 * l];
    const float nh0 = ed * h.x + (1.f - ed) * r0;
    const float nh1 = ed * h.y + (1.f - ed) * r1;
    *(float2*)&g_h[off + 2 * l] = make_float2(nh0, nh1);
    const float2 ep = *(const float2*)&g_ep[off + 2 * l];
    const float p0 = tanhfast(nh0 * ep.x);
    const float p1 = tanhfast(nh1 * ep.y);
    *(float2*)&pm_out[off + 2 * l] = make_float2(p0, p1);

    if (n < C_) {   // emit the 4 timesteps this update covers
        #pragma unroll
        for (int tt = 0; tt < 4; tt++) {
            const size_t oo = (((size_t)b * T_ + t0 + tt) * C_ + n) * DD + 2 * l;
            *(float2*)&out[oo] = make_float2(p0, p1);
        }
    }
}

// =============================================================================
extern "C" void kernel_launch(void* const* d_in, const int* in_sizes, int n_in,
                              void* d_out, int out_size)
{
    const float* cc    = (const float*)d_in[0];
    const float* h_in  = (const float*)d_in[1];
    const float* pm_in = (const float*)d_in[2];
    const float* tp    = (const float*)d_in[3];
    const float* tk    = (const float*)d_in[4];
    const float* prim  = (const float*)d_in[5];
    const float* keyp  = (const float*)d_in[6];
    const float* dlog  = (const float*)d_in[7];
    const float* bw    = (const float*)d_in[8];
    const float* gw    = (const float*)d_in[9];
    const float* fc1w  = (const float*)d_in[10];
    const float* fc1b  = (const float*)d_in[11];
    const float* fc2w  = (const float*)d_in[12];
    const float* fc2b  = (const float*)d_in[13];
    const float* mll   = (const float*)d_in[14];
    const int*   conn  = (const int*)d_in[15];
    float* out = (float*)d_out;

    modk<<<NN, 512>>>(h_in, pm_in, tp, tk, prim, keyp, dlog,
                      fc1w, fc1b, fc2w, fc2b, mll);

    // stride = 4 (fixed by setup): updates at t = 0,4,...,28; output replicated x4
    for (int u = 0; u < 8; u++) {
        stepk<<<NN, 256>>>(u & 1, 4 * u, cc, bw, gw, conn, out);
    }
}

// round 5
// speedup vs baseline: 1.4548x; 1.4548x over previous
#include <cuda_runtime.h>
#include <math.h>

#define BS   8
#define T_   32
#define C_   64
#define NN   4096
#define KK   32
#define DD   64
#define HH   64
#define FIN  320   // 5*D

// ---------------- persistent scratch (no allocation allowed) ----------------
__device__ float g_pm[2][BS * NN * DD];   // double-buffered messages
__device__ float g_h [BS * NN * DD];      // hidden state (in-place per update)
__device__ float g_ep[BS * NN * DD];      // eff_prim
__device__ float g_ek[BS * NN * DD];      // eff_key
__device__ float g_ed[BS * NN];           // eff_decay (scalar per b,n)

// fast sigmoid: RCP-based division, err ~2ulp
__device__ __forceinline__ float sigf(float x) {
    return __fdividef(1.f, 1.f + __expf(-x));
}
// fast tanh: 1 - 2/(e^{2x}+1).  ~6 instr / 2 MUFU, rel err ~1e-6.
// Saturates correctly: x->+inf => e=inf => 1; x->-inf => e=0 => -1.
__device__ __forceinline__ float tanhfast(float x) {
    const float e = __expf(2.f * x);
    return 1.f - __fdividef(2.f, e + 1.f);
}

// =============================================================================
// Kernel A: modulator MLP + state init.  One CTA per neuron n, 512 threads.
// =============================================================================
__global__ void __launch_bounds__(512) modk(
    const float* __restrict__ h_in, const float* __restrict__ pm_in,
    const float* __restrict__ tp,   const float* __restrict__ tk,
    const float* __restrict__ prim, const float* __restrict__ keyp,
    const float* __restrict__ dlog, const float* __restrict__ fc1w,
    const float* __restrict__ fc1b, const float* __restrict__ fc2w,
    const float* __restrict__ fc2b, const float* __restrict__ mll)
{
    const int n   = blockIdx.x;
    const int tid = threadIdx.x;

    __shared__ __align__(16) float s_in[FIN * 12];      // [j][b] pad 12 (float4-friendly)
    __shared__ float s_part[8 * 8 * 64];                // [seg][b][h]
    __shared__ float s_x[8 * 64];                       // tanh(fc1) activations
    __shared__ float s_o[24];                           // fc2 outputs [b][3]
    __shared__ float s_norm[16];                        // [b][{prim,key}]

    // ---- stage mod_input transposed: s_in[j*12 + b] ----
    for (int idx = tid; idx < BS * FIN; idx += 512) {
        const int b = idx / FIN, j = idx % FIN;
        float v;
        if      (j <  64) v = h_in[((size_t)b * NN + n) * DD + j];
        else if (j < 128) v = tp  [((size_t)b * NN + n) * DD + j - 64];
        else if (j < 192) v = tk  [((size_t)b * NN + n) * DD + j - 128];
        else if (j < 256) v = prim[(size_t)n * DD + j - 192];
        else              v = keyp[(size_t)n * DD + j - 256];
        s_in[j * 12 + b] = v;
    }
    __syncthreads();

    // ---- fc1: thread (seg,h) covers j in [seg*40, seg*40+40) for ALL 8 batches ----
    {
        const int seg = tid >> 6, hh = tid & 63;
        float a0=0,a1=0,a2=0,a3=0,a4=0,a5=0,a6=0,a7=0;
        const float* W = fc1w + (size_t)n * FIN * HH + hh;
        const int j0 = seg * 40;
        #pragma unroll 8
        for (int jj = 0; jj < 40; jj++) {
            const int j = j0 + jj;
            const float w = W[(size_t)j * HH];
            const float4 i0 = *(const float4*)&s_in[j * 12];
            const float4 i1 = *(const float4*)&s_in[j * 12 + 4];
            a0 += w * i0.x; a1 += w * i0.y; a2 += w * i0.z; a3 += w * i0.w;
            a4 += w * i1.x; a5 += w * i1.y; a6 += w * i1.z; a7 += w * i1.w;
        }
        float acc[8] = {a0,a1,a2,a3,a4,a5,a6,a7};
        #pragma unroll
        for (int b = 0; b < 8; b++)
            s_part[(seg * 8 + b) * 64 + hh] = acc[b];
    }
    __syncthreads();

    // ---- reduce segments, bias, tanh ----
    {
        const int b = tid >> 6, h = tid & 63;
        float s = 0.f;
        #pragma unroll
        for (int seg = 0; seg < 8; seg++) s += s_part[(seg * 8 + b) * 64 + h];
        s_x[b * 64 + h] = tanhfast(s + fc1b[(size_t)n * HH + h]);
    }
    __syncthreads();

    // ---- fc2 (24 threads) + trace norms (threads 32..47) ----
    if (tid < 24) {
        const int b = tid / 3, o = tid % 3;
        float acc = fc2b[(size_t)n * 3 + o];
        #pragma unroll 8
        for (int h = 0; h < 64; h++)
            acc += s_x[b * 64 + h] * fc2w[((size_t)n * 64 + h) * 3 + o];
        s_o[b * 3 + o] = acc;
    } else if (tid >= 32 && tid < 48) {
        const int q = tid - 32, b = q >> 1, which = q & 1;
        float s = 0.f;
        const int base = 64 + which * 64;
        #pragma unroll 8
        for (int d = 0; d < 64; d++) {
            const float v = s_in[(base + d) * 12 + b];
            s += v * v;
        }
        s_norm[b * 2 + which] = fmaxf(sqrtf(s), 1e-8f);
    }
    __syncthreads();

    // ---- finalize eff_* and init state ----
    {
        const int b = tid >> 6, d = tid & 63;
        const float mod_lr = sigf(mll[0]);
        const float gp = tanhfast(s_o[b * 3 + 0]);
        const float gk = tanhfast(s_o[b * 3 + 1]);
        const float dm = s_o[b * 3 + 2];
        const float tpv = s_in[(64 + d) * 12 + b];
        const float tkv = s_in[(128 + d) * 12 + b];
        const size_t off = ((size_t)b * NN + n) * DD + d;
        g_ep[off] = prim[(size_t)n * DD + d] + mod_lr * gp * (tpv / s_norm[b * 2 + 0]);
        g_ek[off] = keyp[(size_t)n * DD + d] + mod_lr * gk * (tkv / s_norm[b * 2 + 1]);
        g_h [off] = s_in[d * 12 + b];
        g_pm[0][off] = pm_in[off];
        if (d == 0) g_ed[(size_t)b * NN + n] = sigf(dlog[n] + dm);
    }
}

// =============================================================================
// Kernel B: one scan update.  One CTA per neuron n, 8 warps = 8 batches.
// Messages live entirely in registers (lane l owns d=2l,2l+1); sims via a
// 5-stage butterfly multi-reduce (8 sims per chunk).  smem = 9.3 KB static.
// NOTE: no occupancy cap — 64 regs / 4 CTAs/SM.  Capping to 48 regs (R4)
// spilled the gather batch and regressed 35%; registers are the MLP here.
// =============================================================================
__global__ void __launch_bounds__(256) stepk(
    int parity, int t0,
    const float* __restrict__ cc, const float* __restrict__ bw,
    const float* __restrict__ gw, const int* __restrict__ conn,
    float* __restrict__ out)
{
    __shared__ float s_bw[2048];   // [k][d]
    __shared__ float s_gw[256];    // [nb][d]
    __shared__ int   s_idx[32];

    const int n   = blockIdx.x;
    const int tid = threadIdx.x;
    const int b   = tid >> 5;
    const int l   = tid & 31;

    const float* pm_in  = g_pm[parity];
    float*       pm_out = g_pm[parity ^ 1];

    #pragma unroll
    for (int i = 0; i < 8; i++) s_bw[tid + 256 * i] = bw[(size_t)n * 2048 + tid + 256 * i];
    s_gw[tid] = gw[(size_t)n * 256 + tid];
    if (tid < 32) s_idx[tid] = conn[(size_t)n * KK + tid];

    const size_t off = ((size_t)b * NN + n) * DD;
    const float2 key = *(const float2*)&g_ek[off + 2 * l];
    __syncthreads();

    const float* pmb = pm_in + (size_t)b * NN * DD;
    float2 accv[4];

    #pragma unroll
    for (int c = 0; c < 4; c++) {
        // ---- gather 8 messages: lane l holds d=2l, 2l+1 of each ----
        float2 m[8];
        #pragma unroll
        for (int kk = 0; kk < 8; kk++) {
            const int src = s_idx[c * 8 + kk];
            m[kk] = __ldg((const float2*)&pmb[src * DD + 2 * l]);
        }

        // ---- per-lane sim partials ----
        float v[8];
        #pragma unroll
        for (int kk = 0; kk < 8; kk++)
            v[kk] = key.x * m[kk].x + key.y * m[kk].y;

        // ---- butterfly multi-reduce: 8 sums over 32 lanes in 5 stages ----
        {
            const bool h16 = (l & 16);
            #pragma unroll
            for (int i = 0; i < 4; i++) {
                const float keep = h16 ? v[4 + i] : v[i];
                const float send = h16 ? v[i]     : v[4 + i];
                v[i] = keep + __shfl_xor_sync(0xffffffffu, send, 16);
            }
            const bool h8 = (l & 8);
            #pragma unroll
            for (int i = 0; i < 2; i++) {
                const float keep = h8 ? v[2 + i] : v[i];
                const float send = h8 ? v[i]     : v[2 + i];
                v[i] = keep + __shfl_xor_sync(0xffffffffu, send, 8);
            }
            const bool h4 = (l & 4);
            {
                const float keep = h4 ? v[1] : v[0];
                const float send = h4 ? v[0] : v[1];
                v[0] = keep + __shfl_xor_sync(0xffffffffu, send, 4);
            }
            v[0] += __shfl_xor_sync(0xffffffffu, v[0], 2);
            v[0] += __shfl_xor_sync(0xffffffffu, v[0], 1);
        }
        // lane l now holds sim for kk = (l >> 2) & 7
        const float w = sigf(v[0]);

        // ---- weighted + branch partial sums ----
        float ax = 0.f, ay = 0.f;
        #pragma unroll
        for (int kk = 0; kk < 8; kk++) {
            const float wk = __shfl_sync(0xffffffffu, w, kk << 2);
            const float2 bwv = *(const float2*)&s_bw[(c * 8 + kk) * 64 + 2 * l];
            ax += (wk * m[kk].x) * bwv.x;
            ay += (wk * m[kk].y) * bwv.y;
        }
        accv[c].x = ax; accv[c].y = ay;
    }

    // ---- branch tanh -> group sum -> group tanh (ng=1, mean = identity) ----
    float r0 = 0.f, r1 = 0.f;
    #pragma unroll
    for (int nb = 0; nb < 4; nb++) {
        const float2 gwv = *(const float2*)&s_gw[nb * 64 + 2 * l];
        r0 += tanhfast(accv[nb].x) * gwv.x;
        r1 += tanhfast(accv[nb].y) * gwv.y;
    }
    r0 = tanhfast(r0);
    r1 = tanhfast(r1);

    if (n < C_) {   // cc injection on first C neurons
        const float2 ccv = *(const float2*)&cc[(((size_t)b * T_ + t0) * C_ + n) * DD + 2 * l];
        r0 += ccv.x;
        r1 += ccv.y;
    }

    // ---- h / message update ----
    const float ed = g_ed[(size_t)b * NN + n];
    const float2 h = *(const float2*)&g_h[off + 2 * l];
    const float nh0 = ed * h.x + (1.f - ed) * r0;
    const float nh1 = ed * h.y + (1.f - ed) * r1;
    *(float2*)&g_h[off + 2 * l] = make_float2(nh0, nh1);
    const float2 ep = *(const float2*)&g_ep[off + 2 * l];
    const float p0 = tanhfast(nh0 * ep.x);
    const float p1 = tanhfast(nh1 * ep.y);
    *(float2*)&pm_out[off + 2 * l] = make_float2(p0, p1);

    if (n < C_) {   // emit the 4 timesteps this update covers
        #pragma unroll
        for (int tt = 0; tt < 4; tt++) {
            const size_t oo = (((size_t)b * T_ + t0 + tt) * C_ + n) * DD + 2 * l;
            *(float2*)&out[oo] = make_float2(p0, p1);
        }
    }
}

// =============================================================================
extern "C" void kernel_launch(void* const* d_in, const int* in_sizes, int n_in,
                              void* d_out, int out_size)
{
    const float* cc    = (const float*)d_in[0];
    const float* h_in  = (const float*)d_in[1];
    const float* pm_in = (const float*)d_in[2];
    const float* tp    = (const float*)d_in[3];
    const float* tk    = (const float*)d_in[4];
    const float* prim  = (const float*)d_in[5];
    const float* keyp  = (const float*)d_in[6];
    const float* dlog  = (const float*)d_in[7];
    const float* bw    = (const float*)d_in[8];
    const float* gw    = (const float*)d_in[9];
    const float* fc1w  = (const float*)d_in[10];
    const float* fc1b  = (const float*)d_in[11];
    const float* fc2w  = (const float*)d_in[12];
    const float* fc2b  = (const float*)d_in[13];
    const float* mll   = (const float*)d_in[14];
    const int*   conn  = (const int*)d_in[15];
    float* out = (float*)d_out;

    modk<<<NN, 512>>>(h_in, pm_in, tp, tk, prim, keyp, dlog,
                      fc1w, fc1b, fc2w, fc2b, mll);

    // stride = 4 (fixed by setup): updates at t = 0,4,...,28; output replicated x4
    for (int u = 0; u < 8; u++) {
        stepk<<<NN, 256>>>(u & 1, 4 * u, cc, bw, gw, conn, out);
    }
}

// round 6
// speedup vs baseline: 1.4754x; 1.0141x over previous
#include <cuda_runtime.h>
#include <math.h>

#define BS   8
#define T_   32
#define C_   64
#define NN   4096
#define KK   32
#define DD   64
#define HH   64
#define FIN  320   // 5*D

// ---------------- persistent scratch (no allocation allowed) ----------------
__device__ float g_pm[2][BS * NN * DD];   // double-buffered messages
__device__ float g_h [BS * NN * DD];      // hidden state (in-place per update)
__device__ float g_ep[BS * NN * DD];      // eff_prim
__device__ float g_ek[BS * NN * DD];      // eff_key
__device__ float g_ed[BS * NN];           // eff_decay (scalar per b,n)

// fast sigmoid: RCP-based division, err ~2ulp
__device__ __forceinline__ float sigf(float x) {
    return __fdividef(1.f, 1.f + __expf(-x));
}
// fast tanh: 1 - 2/(e^{2x}+1).  Saturates correctly at +/-inf.
__device__ __forceinline__ float tanhfast(float x) {
    const float e = __expf(2.f * x);
    return 1.f - __fdividef(2.f, e + 1.f);
}

// ---- packed f32x2 helpers (Blackwell) ----
typedef unsigned long long u64;
__device__ __forceinline__ u64 pk2(float lo, float hi) {
    u64 r;
    asm("mov.b64 %0, {%1, %2};" : "=l"(r) : "f"(lo), "f"(hi));
    return r;
}
__device__ __forceinline__ float2 upk2(u64 v) {
    float2 r;
    asm("mov.b64 {%0, %1}, %2;" : "=f"(r.x), "=f"(r.y) : "l"(v));
    return r;
}
__device__ __forceinline__ u64 mul2(u64 a, u64 b) {
    u64 r;
    asm("mul.rn.f32x2 %0, %1, %2;" : "=l"(r) : "l"(a), "l"(b));
    return r;
}
__device__ __forceinline__ u64 fma2(u64 a, u64 b, u64 c) {
    u64 r;
    asm("fma.rn.f32x2 %0, %1, %2, %3;" : "=l"(r) : "l"(a), "l"(b), "l"(c));
    return r;
}

// =============================================================================
// Kernel A: modulator MLP + state init.  One CTA per neuron n, 512 threads.
// =============================================================================
__global__ void __launch_bounds__(512) modk(
    const float* __restrict__ h_in, const float* __restrict__ pm_in,
    const float* __restrict__ tp,   const float* __restrict__ tk,
    const float* __restrict__ prim, const float* __restrict__ keyp,
    const float* __restrict__ dlog, const float* __restrict__ fc1w,
    const float* __restrict__ fc1b, const float* __restrict__ fc2w,
    const float* __restrict__ fc2b, const float* __restrict__ mll)
{
    const int n   = blockIdx.x;
    const int tid = threadIdx.x;

    __shared__ __align__(16) float s_in[FIN * 12];      // [j][b] pad 12 (float4-friendly)
    __shared__ float s_part[8 * 8 * 64];                // [seg][b][h]
    __shared__ float s_x[8 * 64];                       // tanh(fc1) activations
    __shared__ float s_o[24];                           // fc2 outputs [b][3]
    __shared__ float s_norm[16];                        // [b][{prim,key}]

    // ---- stage mod_input transposed: s_in[j*12 + b] ----
    for (int idx = tid; idx < BS * FIN; idx += 512) {
        const int b = idx / FIN, j = idx % FIN;
        float v;
        if      (j <  64) v = h_in[((size_t)b * NN + n) * DD + j];
        else if (j < 128) v = tp  [((size_t)b * NN + n) * DD + j - 64];
        else if (j < 192) v = tk  [((size_t)b * NN + n) * DD + j - 128];
        else if (j < 256) v = prim[(size_t)n * DD + j - 192];
        else              v = keyp[(size_t)n * DD + j - 256];
        s_in[j * 12 + b] = v;
    }
    __syncthreads();

    // ---- fc1: thread (seg,h) covers j in [seg*40, seg*40+40) for ALL 8 batches ----
    {
        const int seg = tid >> 6, hh = tid & 63;
        float a0=0,a1=0,a2=0,a3=0,a4=0,a5=0,a6=0,a7=0;
        const float* W = fc1w + (size_t)n * FIN * HH + hh;
        const int j0 = seg * 40;
        #pragma unroll 8
        for (int jj = 0; jj < 40; jj++) {
            const int j = j0 + jj;
            const float w = W[(size_t)j * HH];
            const float4 i0 = *(const float4*)&s_in[j * 12];
            const float4 i1 = *(const float4*)&s_in[j * 12 + 4];
            a0 += w * i0.x; a1 += w * i0.y; a2 += w * i0.z; a3 += w * i0.w;
            a4 += w * i1.x; a5 += w * i1.y; a6 += w * i1.z; a7 += w * i1.w;
        }
        float acc[8] = {a0,a1,a2,a3,a4,a5,a6,a7};
        #pragma unroll
        for (int b = 0; b < 8; b++)
            s_part[(seg * 8 + b) * 64 + hh] = acc[b];
    }
    __syncthreads();

    // ---- reduce segments, bias, tanh ----
    {
        const int b = tid >> 6, h = tid & 63;
        float s = 0.f;
        #pragma unroll
        for (int seg = 0; seg < 8; seg++) s += s_part[(seg * 8 + b) * 64 + h];
        s_x[b * 64 + h] = tanhfast(s + fc1b[(size_t)n * HH + h]);
    }
    __syncthreads();

    // ---- fc2 (24 threads) + trace norms (threads 32..47) ----
    if (tid < 24) {
        const int b = tid / 3, o = tid % 3;
        float acc = fc2b[(size_t)n * 3 + o];
        #pragma unroll 8
        for (int h = 0; h < 64; h++)
            acc += s_x[b * 64 + h] * fc2w[((size_t)n * 64 + h) * 3 + o];
        s_o[b * 3 + o] = acc;
    } else if (tid >= 32 && tid < 48) {
        const int q = tid - 32, b = q >> 1, which = q & 1;
        float s = 0.f;
        const int base = 64 + which * 64;
        #pragma unroll 8
        for (int d = 0; d < 64; d++) {
            const float v = s_in[(base + d) * 12 + b];
            s += v * v;
        }
        s_norm[b * 2 + which] = fmaxf(sqrtf(s), 1e-8f);
    }
    __syncthreads();

    // ---- finalize eff_* and init state ----
    {
        const int b = tid >> 6, d = tid & 63;
        const float mod_lr = sigf(mll[0]);
        const float gp = tanhfast(s_o[b * 3 + 0]);
        const float gk = tanhfast(s_o[b * 3 + 1]);
        const float dm = s_o[b * 3 + 2];
        const float tpv = s_in[(64 + d) * 12 + b];
        const float tkv = s_in[(128 + d) * 12 + b];
        const size_t off = ((size_t)b * NN + n) * DD + d;
        g_ep[off] = prim[(size_t)n * DD + d] + mod_lr * gp * (tpv / s_norm[b * 2 + 0]);
        g_ek[off] = keyp[(size_t)n * DD + d] + mod_lr * gk * (tkv / s_norm[b * 2 + 1]);
        g_h [off] = s_in[d * 12 + b];
        g_pm[0][off] = pm_in[off];
        if (d == 0) g_ed[(size_t)b * NN + n] = sigf(dlog[n] + dm);
    }
}

// =============================================================================
// Kernel B: one scan update.  One CTA per neuron n, 8 warps = 8 batches.
// Messages in registers; sims via 5-stage butterfly multi-reduce.
// Software-pipelined: t = m*bw premul frees m, next chunk's gather overlaps
// the butterfly + accumulation.  Packed f32x2 mul/fma in the hot path.
// __launch_bounds__(256,4): 64-reg ceiling (R3 config) — do NOT cap tighter,
// 48 regs spilled the gather batch in R4 (-35%).
// =============================================================================
__global__ void __launch_bounds__(256, 4) stepk(
    int parity, int t0,
    const float* __restrict__ cc, const float* __restrict__ bw,
    const float* __restrict__ gw, const int* __restrict__ conn,
    float* __restrict__ out)
{
    __shared__ float s_bw[2048];   // [k][d]
    __shared__ float s_gw[256];    // [nb][d]
    __shared__ int   s_idx[32];

    const int n   = blockIdx.x;
    const int tid = threadIdx.x;
    const int b   = tid >> 5;
    const int l   = tid & 31;

    const float* pm_in  = g_pm[parity];
    float*       pm_out = g_pm[parity ^ 1];

    #pragma unroll
    for (int i = 0; i < 8; i++) s_bw[tid + 256 * i] = bw[(size_t)n * 2048 + tid + 256 * i];
    s_gw[tid] = gw[(size_t)n * 256 + tid];
    if (tid < 32) s_idx[tid] = conn[(size_t)n * KK + tid];

    const size_t off = ((size_t)b * NN + n) * DD;
    const float2 key = *(const float2*)&g_ek[off + 2 * l];
    __syncthreads();

    const float* pmb = pm_in + (size_t)b * NN * DD;
    u64 accp[4];

    // ---- prologue: gather chunk 0 (lane l holds d=2l,2l+1 of each msg) ----
    float2 m[8];
    #pragma unroll
    for (int kk = 0; kk < 8; kk++)
        m[kk] = __ldg((const float2*)&pmb[s_idx[kk] * DD + 2 * l]);

    #pragma unroll
    for (int c = 0; c < 4; c++) {
        // ---- phase 1: sim partials + premul t = m*bw (m dies here) ----
        float v[8];
        u64 t[8];
        #pragma unroll
        for (int kk = 0; kk < 8; kk++) {
            v[kk] = key.x * m[kk].x + key.y * m[kk].y;
            const float2 bwv = *(const float2*)&s_bw[(c * 8 + kk) * 64 + 2 * l];
            t[kk] = mul2(pk2(m[kk].x, m[kk].y), pk2(bwv.x, bwv.y));
        }

        // ---- phase 2: prefetch next chunk's gathers (overlaps phases 3-4) ----
        if (c < 3) {
            #pragma unroll
            for (int kk = 0; kk < 8; kk++)
                m[kk] = __ldg((const float2*)&pmb[s_idx[(c + 1) * 8 + kk] * DD + 2 * l]);
        }

        // ---- phase 3: butterfly multi-reduce (8 sums over 32 lanes) ----
        {
            const bool h16 = (l & 16);
            #pragma unroll
            for (int i = 0; i < 4; i++) {
                const float keep = h16 ? v[4 + i] : v[i];
                const float send = h16 ? v[i]     : v[4 + i];
                v[i] = keep + __shfl_xor_sync(0xffffffffu, send, 16);
            }
            const bool h8 = (l & 8);
            #pragma unroll
            for (int i = 0; i < 2; i++) {
                const float keep = h8 ? v[2 + i] : v[i];
                const float send = h8 ? v[i]     : v[2 + i];
                v[i] = keep + __shfl_xor_sync(0xffffffffu, send, 8);
            }
            const bool h4 = (l & 4);
            {
                const float keep = h4 ? v[1] : v[0];
                const float send = h4 ? v[0] : v[1];
                v[0] = keep + __shfl_xor_sync(0xffffffffu, send, 4);
            }
            v[0] += __shfl_xor_sync(0xffffffffu, v[0], 2);
            v[0] += __shfl_xor_sync(0xffffffffu, v[0], 1);
        }
        // lane l now holds sim for kk = (l >> 2) & 7
        const float w = sigf(v[0]);

        // ---- phase 4: packed accumulate (chunk c == branch c) ----
        u64 a = 0ull;
        #pragma unroll
        for (int kk = 0; kk < 8; kk++) {
            const float wk = __shfl_sync(0xffffffffu, w, kk << 2);
            a = fma2(t[kk], pk2(wk, wk), a);
        }
        accp[c] = a;
    }

    // ---- branch tanh -> group sum -> group tanh (ng=1, mean = identity) ----
    float r0 = 0.f, r1 = 0.f;
    #pragma unroll
    for (int nb = 0; nb < 4; nb++) {
        const float2 av  = upk2(accp[nb]);
        const float2 gwv = *(const float2*)&s_gw[nb * 64 + 2 * l];
        r0 += tanhfast(av.x) * gwv.x;
        r1 += tanhfast(av.y) * gwv.y;
    }
    r0 = tanhfast(r0);
    r1 = tanhfast(r1);

    if (n < C_) {   // cc injection on first C neurons
        const float2 ccv = *(const float2*)&cc[(((size_t)b * T_ + t0) * C_ + n) * DD + 2 * l];
        r0 += ccv.x;
        r1 += ccv.y;
    }

    // ---- h / message update ----
    const float ed = g_ed[(size_t)b * NN + n];
    const float2 h = *(const float2*)&g_h[off + 2 * l];
    const float nh0 = ed * h.x + (1.f - ed) * r0;
    const float nh1 = ed * h.y + (1.f - ed) * r1;
    *(float2*)&g_h[off + 2 * l] = make_float2(nh0, nh1);
    const float2 ep = *(const float2*)&g_ep[off + 2 * l];
    const float p0 = tanhfast(nh0 * ep.x);
    const float p1 = tanhfast(nh1 * ep.y);
    *(float2*)&pm_out[off + 2 * l] = make_float2(p0, p1);

    if (n < C_) {   // emit the 4 timesteps this update covers
        #pragma unroll
        for (int tt = 0; tt < 4; tt++) {
            const size_t oo = (((size_t)b * T_ + t0 + tt) * C_ + n) * DD + 2 * l;
            *(float2*)&out[oo] = make_float2(p0, p1);
        }
    }
}

// =============================================================================
extern "C" void kernel_launch(void* const* d_in, const int* in_sizes, int n_in,
                              void* d_out, int out_size)
{
    const float* cc    = (const float*)d_in[0];
    const float* h_in  = (const float*)d_in[1];
    const float* pm_in = (const float*)d_in[2];
    const float* tp    = (const float*)d_in[3];
    const float* tk    = (const float*)d_in[4];
    const float* prim  = (const float*)d_in[5];
    const float* keyp  = (const float*)d_in[6];
    const float* dlog  = (const float*)d_in[7];
    const float* bw    = (const float*)d_in[8];
    const float* gw    = (const float*)d_in[9];
    const float* fc1w  = (const float*)d_in[10];
    const float* fc1b  = (const float*)d_in[11];
    const float* fc2w  = (const float*)d_in[12];
    const float* fc2b  = (const float*)d_in[13];
    const float* mll   = (const float*)d_in[14];
    const int*   conn  = (const int*)d_in[15];
    float* out = (float*)d_out;

    modk<<<NN, 512>>>(h_in, pm_in, tp, tk, prim, keyp, dlog,
                      fc1w, fc1b, fc2w, fc2b, mll);

    // stride = 4 (fixed by setup): updates at t = 0,4,...,28; output replicated x4
    for (int u = 0; u < 8; u++) {
        stepk<<<NN, 256>>>(u & 1, 4 * u, cc, bw, gw, conn, out);
    }
}

// round 7
// speedup vs baseline: 1.6131x; 1.0934x over previous
#include <cuda_runtime.h>
#include <cuda_fp16.h>
#include <math.h>

#define BS   8
#define T_   32
#define C_   64
#define NN   4096
#define KK   32
#define DD   64
#define HH   64
#define FIN  320   // 5*D

// ---------------- persistent scratch (no allocation allowed) ----------------
__device__ __half g_pmh[2][BS * NN * DD];  // double-buffered messages (fp16)
__device__ float  g_h [BS * NN * DD];      // hidden state (fp32, in-place)
__device__ float  g_ep[BS * NN * DD];      // eff_prim
__device__ float  g_ek[BS * NN * DD];      // eff_key
__device__ float  g_ed[BS * NN];           // eff_decay (scalar per b,n)

// fast sigmoid
__device__ __forceinline__ float sigf(float x) {
    return __fdividef(1.f, 1.f + __expf(-x));
}
// fast tanh: 1 - 2/(e^{2x}+1).  Saturates correctly at +/-inf.
__device__ __forceinline__ float tanhfast(float x) {
    const float e = __expf(2.f * x);
    return 1.f - __fdividef(2.f, e + 1.f);
}

// ---- packed f32x2 helpers (Blackwell) ----
typedef unsigned long long u64;
__device__ __forceinline__ u64 pk2(float lo, float hi) {
    u64 r;
    asm("mov.b64 %0, {%1, %2};" : "=l"(r) : "f"(lo), "f"(hi));
    return r;
}
__device__ __forceinline__ float2 upk2(u64 v) {
    float2 r;
    asm("mov.b64 {%0, %1}, %2;" : "=f"(r.x), "=f"(r.y) : "l"(v));
    return r;
}
__device__ __forceinline__ u64 mul2(u64 a, u64 b) {
    u64 r;
    asm("mul.rn.f32x2 %0, %1, %2;" : "=l"(r) : "l"(a), "l"(b));
    return r;
}
__device__ __forceinline__ u64 fma2(u64 a, u64 b, u64 c) {
    u64 r;
    asm("fma.rn.f32x2 %0, %1, %2, %3;" : "=l"(r) : "l"(a), "l"(b), "l"(c));
    return r;
}

// =============================================================================
// Kernel A: modulator MLP + state init.  One CTA per neuron n, 512 threads.
// =============================================================================
__global__ void __launch_bounds__(512) modk(
    const float* __restrict__ h_in, const float* __restrict__ pm_in,
    const float* __restrict__ tp,   const float* __restrict__ tk,
    const float* __restrict__ prim, const float* __restrict__ keyp,
    const float* __restrict__ dlog, const float* __restrict__ fc1w,
    const float* __restrict__ fc1b, const float* __restrict__ fc2w,
    const float* __restrict__ fc2b, const float* __restrict__ mll)
{
    const int n   = blockIdx.x;
    const int tid = threadIdx.x;

    __shared__ __align__(16) float s_in[FIN * 12];      // [j][b] pad 12 (float4-friendly)
    __shared__ float s_part[8 * 8 * 64];                // [seg][b][h]
    __shared__ float s_x[8 * 64];                       // tanh(fc1) activations
    __shared__ float s_o[24];                           // fc2 outputs [b][3]
    __shared__ float s_norm[16];                        // [b][{prim,key}]

    // ---- stage mod_input transposed: s_in[j*12 + b] ----
    for (int idx = tid; idx < BS * FIN; idx += 512) {
        const int b = idx / FIN, j = idx % FIN;
        float v;
        if      (j <  64) v = h_in[((size_t)b * NN + n) * DD + j];
        else if (j < 128) v = tp  [((size_t)b * NN + n) * DD + j - 64];
        else if (j < 192) v = tk  [((size_t)b * NN + n) * DD + j - 128];
        else if (j < 256) v = prim[(size_t)n * DD + j - 192];
        else              v = keyp[(size_t)n * DD + j - 256];
        s_in[j * 12 + b] = v;
    }
    __syncthreads();

    // ---- fc1: thread (seg,h) covers j in [seg*40, seg*40+40) for ALL 8 batches ----
    {
        const int seg = tid >> 6, hh = tid & 63;
        float a0=0,a1=0,a2=0,a3=0,a4=0,a5=0,a6=0,a7=0;
        const float* W = fc1w + (size_t)n * FIN * HH + hh;
        const int j0 = seg * 40;
        #pragma unroll 8
        for (int jj = 0; jj < 40; jj++) {
            const int j = j0 + jj;
            const float w = W[(size_t)j * HH];
            const float4 i0 = *(const float4*)&s_in[j * 12];
            const float4 i1 = *(const float4*)&s_in[j * 12 + 4];
            a0 += w * i0.x; a1 += w * i0.y; a2 += w * i0.z; a3 += w * i0.w;
            a4 += w * i1.x; a5 += w * i1.y; a6 += w * i1.z; a7 += w * i1.w;
        }
        float acc[8] = {a0,a1,a2,a3,a4,a5,a6,a7};
        #pragma unroll
        for (int b = 0; b < 8; b++)
            s_part[(seg * 8 + b) * 64 + hh] = acc[b];
    }
    __syncthreads();

    // ---- reduce segments, bias, tanh ----
    {
        const int b = tid >> 6, h = tid & 63;
        float s = 0.f;
        #pragma unroll
        for (int seg = 0; seg < 8; seg++) s += s_part[(seg * 8 + b) * 64 + h];
        s_x[b * 64 + h] = tanhfast(s + fc1b[(size_t)n * HH + h]);
    }
    __syncthreads();

    // ---- fc2 (24 threads) + trace norms (threads 32..47) ----
    if (tid < 24) {
        const int b = tid / 3, o = tid % 3;
        float acc = fc2b[(size_t)n * 3 + o];
        #pragma unroll 8
        for (int h = 0; h < 64; h++)
            acc += s_x[b * 64 + h] * fc2w[((size_t)n * 64 + h) * 3 + o];
        s_o[b * 3 + o] = acc;
    } else if (tid >= 32 && tid < 48) {
        const int q = tid - 32, b = q >> 1, which = q & 1;
        float s = 0.f;
        const int base = 64 + which * 64;
        #pragma unroll 8
        for (int d = 0; d < 64; d++) {
            const float v = s_in[(base + d) * 12 + b];
            s += v * v;
        }
        s_norm[b * 2 + which] = fmaxf(sqrtf(s), 1e-8f);
    }
    __syncthreads();

    // ---- finalize eff_* and init state ----
    {
        const int b = tid >> 6, d = tid & 63;
        const float mod_lr = sigf(mll[0]);
        const float gp = tanhfast(s_o[b * 3 + 0]);
        const float gk = tanhfast(s_o[b * 3 + 1]);
        const float dm = s_o[b * 3 + 2];
        const float tpv = s_in[(64 + d) * 12 + b];
        const float tkv = s_in[(128 + d) * 12 + b];
        const size_t off = ((size_t)b * NN + n) * DD + d;
        g_ep[off] = prim[(size_t)n * DD + d] + mod_lr * gp * (tpv / s_norm[b * 2 + 0]);
        g_ek[off] = keyp[(size_t)n * DD + d] + mod_lr * gk * (tkv / s_norm[b * 2 + 1]);
        g_h [off] = s_in[d * 12 + b];
        g_pmh[0][off] = __float2half_rn(pm_in[off]);
        if (d == 0) g_ed[(size_t)b * NN + n] = sigf(dlog[n] + dm);
    }
}

// =============================================================================
// Kernel B: one scan update.  One CTA per neuron n, 8 warps = 8 batches.
// Messages + branch weights stored fp16 (math fp32): halves the L1 bytes that
// R6 showed to be the binding constraint.  Software-pipelined gathers,
// butterfly multi-reduce sims, packed f32x2 accumulate.
// 64-reg ceiling (256,4): 48-reg cap spilled the gather batch in R4 (-35%).
// =============================================================================
__global__ void __launch_bounds__(256, 4) stepk(
    int parity, int t0,
    const float* __restrict__ cc, const float* __restrict__ bw,
    const float* __restrict__ gw, const int* __restrict__ conn,
    float* __restrict__ out)
{
    __shared__ __half2 s_bwh[1024];   // [k][d/2]  fp16 branch weights
    __shared__ float   s_gw[256];     // [nb][d]   fp32 group weights
    __shared__ int     s_idx[32];

    const int n   = blockIdx.x;
    const int tid = threadIdx.x;
    const int b   = tid >> 5;
    const int l   = tid & 31;

    const __half* pm_in  = g_pmh[parity];
    __half*       pm_out = g_pmh[parity ^ 1];

    // fill bw (fp32 global -> fp16 smem), gw, conn
    #pragma unroll
    for (int i = 0; i < 4; i++) {
        const int idx = tid + 256 * i;            // half2 index
        const float2 v = *(const float2*)&bw[(size_t)n * 2048 + 2 * idx];
        s_bwh[idx] = __floats2half2_rn(v.x, v.y);
    }
    s_gw[tid] = gw[(size_t)n * 256 + tid];
    if (tid < 32) s_idx[tid] = conn[(size_t)n * KK + tid];

    const size_t off = ((size_t)b * NN + n) * DD;
    const float2 key = *(const float2*)&g_ek[off + 2 * l];
    __syncthreads();

    const __half2* pmb = (const __half2*)(pm_in + (size_t)b * NN * DD);
    u64 accp[4];

    // ---- prologue: gather chunk 0 (lane l holds d=2l,2l+1 as half2) ----
    __half2 m[8];
    #pragma unroll
    for (int kk = 0; kk < 8; kk++)
        m[kk] = __ldg(&pmb[s_idx[kk] * 32 + l]);

    #pragma unroll
    for (int c = 0; c < 4; c++) {
        // ---- phase 1: convert, sim partials, premul t = m*bw (m dies) ----
        float v[8];
        u64 t[8];
        #pragma unroll
        for (int kk = 0; kk < 8; kk++) {
            const float2 mf  = __half22float2(m[kk]);
            const float2 bwv = __half22float2(s_bwh[(c * 8 + kk) * 32 + l]);
            v[kk] = key.x * mf.x + key.y * mf.y;
            t[kk] = mul2(pk2(mf.x, mf.y), pk2(bwv.x, bwv.y));
        }

        // ---- phase 2: prefetch next chunk's gathers (overlaps 3-4) ----
        if (c < 3) {
            #pragma unroll
            for (int kk = 0; kk < 8; kk++)
                m[kk] = __ldg(&pmb[s_idx[(c + 1) * 8 + kk] * 32 + l]);
        }

        // ---- phase 3: butterfly multi-reduce (8 sums over 32 lanes) ----
        {
            const bool h16 = (l & 16);
            #pragma unroll
            for (int i = 0; i < 4; i++) {
                const float keep = h16 ? v[4 + i] : v[i];
                const float send = h16 ? v[i]     : v[4 + i];
                v[i] = keep + __shfl_xor_sync(0xffffffffu, send, 16);
            }
            const bool h8 = (l & 8);
            #pragma unroll
            for (int i = 0; i < 2; i++) {
                const float keep = h8 ? v[2 + i] : v[i];
                const float send = h8 ? v[i]     : v[2 + i];
                v[i] = keep + __shfl_xor_sync(0xffffffffu, send, 8);
            }
            const bool h4 = (l & 4);
            {
                const float keep = h4 ? v[1] : v[0];
                const float send = h4 ? v[0] : v[1];
                v[0] = keep + __shfl_xor_sync(0xffffffffu, send, 4);
            }
            v[0] += __shfl_xor_sync(0xffffffffu, v[0], 2);
            v[0] += __shfl_xor_sync(0xffffffffu, v[0], 1);
        }
        // lane l holds sim for kk = (l >> 2) & 7
        const float w = sigf(v[0]);

        // ---- phase 4: packed accumulate (chunk c == branch c) ----
        u64 a = 0ull;
        #pragma unroll
        for (int kk = 0; kk < 8; kk++) {
            const float wk = __shfl_sync(0xffffffffu, w, kk << 2);
            a = fma2(t[kk], pk2(wk, wk), a);
        }
        accp[c] = a;
    }

    // ---- branch tanh -> group sum -> group tanh (ng=1, mean = identity) ----
    float r0 = 0.f, r1 = 0.f;
    #pragma unroll
    for (int nb = 0; nb < 4; nb++) {
        const float2 av  = upk2(accp[nb]);
        const float2 gwv = *(const float2*)&s_gw[nb * 64 + 2 * l];
        r0 += tanhfast(av.x) * gwv.x;
        r1 += tanhfast(av.y) * gwv.y;
    }
    r0 = tanhfast(r0);
    r1 = tanhfast(r1);

    if (n < C_) {   // cc injection on first C neurons
        const float2 ccv = *(const float2*)&cc[(((size_t)b * T_ + t0) * C_ + n) * DD + 2 * l];
        r0 += ccv.x;
        r1 += ccv.y;
    }

    // ---- h / message update ----
    const float ed = g_ed[(size_t)b * NN + n];
    const float2 h = *(const float2*)&g_h[off + 2 * l];
    const float nh0 = ed * h.x + (1.f - ed) * r0;
    const float nh1 = ed * h.y + (1.f - ed) * r1;
    *(float2*)&g_h[off + 2 * l] = make_float2(nh0, nh1);
    const float2 ep = *(const float2*)&g_ep[off + 2 * l];
    const float p0 = tanhfast(nh0 * ep.x);
    const float p1 = tanhfast(nh1 * ep.y);
    *((__half2*)(pm_out + off) + l) = __floats2half2_rn(p0, p1);

    if (n < C_) {   // emit the 4 timesteps this update covers (fp32 output)
        #pragma unroll
        for (int tt = 0; tt < 4; tt++) {
            const size_t oo = (((size_t)b * T_ + t0 + tt) * C_ + n) * DD + 2 * l;
            *(float2*)&out[oo] = make_float2(p0, p1);
        }
    }
}

// =============================================================================
extern "C" void kernel_launch(void* const* d_in, const int* in_sizes, int n_in,
                              void* d_out, int out_size)
{
    const float* cc    = (const float*)d_in[0];
    const float* h_in  = (const float*)d_in[1];
    const float* pm_in = (const float*)d_in[2];
    const float* tp    = (const float*)d_in[3];
    const float* tk    = (const float*)d_in[4];
    const float* prim  = (const float*)d_in[5];
    const float* keyp  = (const float*)d_in[6];
    const float* dlog  = (const float*)d_in[7];
    const float* bw    = (const float*)d_in[8];
    const float* gw    = (const float*)d_in[9];
    const float* fc1w  = (const float*)d_in[10];
    const float* fc1b  = (const float*)d_in[11];
    const float* fc2w  = (const float*)d_in[12];
    const float* fc2b  = (const float*)d_in[13];
    const float* mll   = (const float*)d_in[14];
    const int*   conn  = (const int*)d_in[15];
    float* out = (float*)d_out;

    modk<<<NN, 512>>>(h_in, pm_in, tp, tk, prim, keyp, dlog,
                      fc1w, fc1b, fc2w, fc2b, mll);

    // stride = 4 (fixed by setup): updates at t = 0,4,...,28; output replicated x4
    for (int u = 0; u < 8; u++) {
        stepk<<<NN, 256>>>(u & 1, 4 * u, cc, bw, gw, conn, out);
    }
}

// round 8
// speedup vs baseline: 1.6207x; 1.0047x over previous
#include <cuda_runtime.h>
#include <cuda_fp16.h>
#include <math.h>

#define BS   8
#define T_   32
#define C_   64
#define NN   4096
#define KK   32
#define DD   64
#define HH   64
#define FIN  320   // 5*D

// ---------------- persistent scratch (no allocation allowed) ----------------
__device__ __half g_pmh[2][BS * NN * DD];  // double-buffered messages (fp16)
__device__ float  g_h [BS * NN * DD];      // hidden state (fp32, in-place)
__device__ float  g_ep[BS * NN * DD];      // eff_prim
__device__ float  g_ek[BS * NN * DD];      // eff_key
__device__ float  g_ed[BS * NN];           // eff_decay (scalar per b,n)

// fast sigmoid
__device__ __forceinline__ float sigf(float x) {
    return __fdividef(1.f, 1.f + __expf(-x));
}
// fast tanh: 1 - 2/(e^{2x}+1).  Saturates correctly at +/-inf.
__device__ __forceinline__ float tanhfast(float x) {
    const float e = __expf(2.f * x);
    return 1.f - __fdividef(2.f, e + 1.f);
}

// ---- packed f32x2 helpers (Blackwell) ----
typedef unsigned long long u64;
__device__ __forceinline__ u64 pk2(float lo, float hi) {
    u64 r;
    asm("mov.b64 %0, {%1, %2};" : "=l"(r) : "f"(lo), "f"(hi));
    return r;
}
__device__ __forceinline__ float2 upk2(u64 v) {
    float2 r;
    asm("mov.b64 {%0, %1}, %2;" : "=f"(r.x), "=f"(r.y) : "l"(v));
    return r;
}
__device__ __forceinline__ u64 mul2(u64 a, u64 b) {
    u64 r;
    asm("mul.rn.f32x2 %0, %1, %2;" : "=l"(r) : "l"(a), "l"(b));
    return r;
}
__device__ __forceinline__ u64 fma2(u64 a, u64 b, u64 c) {
    u64 r;
    asm("fma.rn.f32x2 %0, %1, %2, %3;" : "=l"(r) : "l"(a), "l"(b), "l"(c));
    return r;
}

// =============================================================================
// Kernel A: modulator MLP + state init.  One CTA per neuron n, 512 threads.
// fc1 hot loop uses packed f32x2 FMA over batch pairs: 10 issue slots per
// 16 scalar FMAs (was 19) -> pushes the kernel to its DRAM roof.
// =============================================================================
__global__ void __launch_bounds__(512) modk(
    const float* __restrict__ h_in, const float* __restrict__ pm_in,
    const float* __restrict__ tp,   const float* __restrict__ tk,
    const float* __restrict__ prim, const float* __restrict__ keyp,
    const float* __restrict__ dlog, const float* __restrict__ fc1w,
    const float* __restrict__ fc1b, const float* __restrict__ fc2w,
    const float* __restrict__ fc2b, const float* __restrict__ mll)
{
    const int n   = blockIdx.x;
    const int tid = threadIdx.x;

    __shared__ __align__(16) float s_in[FIN * 12];      // [j][b] pad 12 (8B-aligned rows)
    __shared__ float s_part[8 * 8 * 64];                // [seg][b][h]
    __shared__ float s_x[8 * 64];                       // tanh(fc1) activations
    __shared__ float s_o[24];                           // fc2 outputs [b][3]
    __shared__ float s_norm[16];                        // [b][{prim,key}]

    // ---- stage mod_input transposed: s_in[j*12 + b] ----
    for (int idx = tid; idx < BS * FIN; idx += 512) {
        const int b = idx / FIN, j = idx % FIN;
        float v;
        if      (j <  64) v = h_in[((size_t)b * NN + n) * DD + j];
        else if (j < 128) v = tp  [((size_t)b * NN + n) * DD + j - 64];
        else if (j < 192) v = tk  [((size_t)b * NN + n) * DD + j - 128];
        else if (j < 256) v = prim[(size_t)n * DD + j - 192];
        else              v = keyp[(size_t)n * DD + j - 256];
        s_in[j * 12 + b] = v;
    }
    __syncthreads();

    // ---- fc1: thread (seg,h) covers j in [seg*40, seg*40+40), packed b-pairs ----
    {
        const int seg = tid >> 6, hh = tid & 63;
        u64 a[4] = {0ull, 0ull, 0ull, 0ull};
        const float* W = fc1w + (size_t)n * FIN * HH + hh;
        const int j0 = seg * 40;
        #pragma unroll 8
        for (int jj = 0; jj < 40; jj++) {
            const int j = j0 + jj;
            const float w = W[(size_t)j * HH];
            const u64 w2 = pk2(w, w);
            const u64* ip = (const u64*)&s_in[j * 12];   // 4 packed batch-pairs
            a[0] = fma2(ip[0], w2, a[0]);
            a[1] = fma2(ip[1], w2, a[1]);
            a[2] = fma2(ip[2], w2, a[2]);
            a[3] = fma2(ip[3], w2, a[3]);
        }
        #pragma unroll
        for (int p = 0; p < 4; p++) {
            const float2 f = upk2(a[p]);
            s_part[((seg * 8) + 2 * p)     * 64 + hh] = f.x;
            s_part[((seg * 8) + 2 * p + 1) * 64 + hh] = f.y;
        }
    }
    __syncthreads();

    // ---- reduce segments, bias, tanh ----
    {
        const int b = tid >> 6, h = tid & 63;
        float s = 0.f;
        #pragma unroll
        for (int seg = 0; seg < 8; seg++) s += s_part[(seg * 8 + b) * 64 + h];
        s_x[b * 64 + h] = tanhfast(s + fc1b[(size_t)n * HH + h]);
    }
    __syncthreads();

    // ---- fc2 (24 threads) + trace norms (threads 32..47) ----
    if (tid < 24) {
        const int b = tid / 3, o = tid % 3;
        float acc = fc2b[(size_t)n * 3 + o];
        #pragma unroll 8
        for (int h = 0; h < 64; h++)
            acc += s_x[b * 64 + h] * fc2w[((size_t)n * 64 + h) * 3 + o];
        s_o[b * 3 + o] = acc;
    } else if (tid >= 32 && tid < 48) {
        const int q = tid - 32, b = q >> 1, which = q & 1;
        float s = 0.f;
        const int base = 64 + which * 64;
        #pragma unroll 8
        for (int d = 0; d < 64; d++) {
            const float v = s_in[(base + d) * 12 + b];
            s += v * v;
        }
        s_norm[b * 2 + which] = fmaxf(sqrtf(s), 1e-8f);
    }
    __syncthreads();

    // ---- finalize eff_* and init state ----
    {
        const int b = tid >> 6, d = tid & 63;
        const float mod_lr = sigf(mll[0]);
        const float gp = tanhfast(s_o[b * 3 + 0]);
        const float gk = tanhfast(s_o[b * 3 + 1]);
        const float dm = s_o[b * 3 + 2];
        const float tpv = s_in[(64 + d) * 12 + b];
        const float tkv = s_in[(128 + d) * 12 + b];
        const size_t off = ((size_t)b * NN + n) * DD + d;
        g_ep[off] = prim[(size_t)n * DD + d] + mod_lr * gp * (tpv / s_norm[b * 2 + 0]);
        g_ek[off] = keyp[(size_t)n * DD + d] + mod_lr * gk * (tkv / s_norm[b * 2 + 1]);
        g_h [off] = s_in[d * 12 + b];
        g_pmh[0][off] = __float2half_rn(pm_in[off]);
        if (d == 0) g_ed[(size_t)b * NN + n] = sigf(dlog[n] + dm);
    }
}

// =============================================================================
// Kernel B: one scan update.  One CTA per neuron n, 8 warps = 8 batches.
// Messages + branch weights stored fp16 (math fp32).  Software-pipelined
// gathers, butterfly multi-reduce sims, packed f32x2 accumulate.
// 64-reg ceiling (256,4): 48-reg cap spilled the gather batch in R4 (-35%).
// =============================================================================
__global__ void __launch_bounds__(256, 4) stepk(
    int parity, int t0,
    const float* __restrict__ cc, const float* __restrict__ bw,
    const float* __restrict__ gw, const int* __restrict__ conn,
    float* __restrict__ out)
{
    __shared__ __half2 s_bwh[1024];   // [k][d/2]  fp16 branch weights
    __shared__ float   s_gw[256];     // [nb][d]   fp32 group weights
    __shared__ int     s_idx[32];

    const int n   = blockIdx.x;
    const int tid = threadIdx.x;
    const int b   = tid >> 5;
    const int l   = tid & 31;

    const __half* pm_in  = g_pmh[parity];
    __half*       pm_out = g_pmh[parity ^ 1];

    // fill bw (fp32 global -> fp16 smem), gw, conn
    #pragma unroll
    for (int i = 0; i < 4; i++) {
        const int idx = tid + 256 * i;            // half2 index
        const float2 v = *(const float2*)&bw[(size_t)n * 2048 + 2 * idx];
        s_bwh[idx] = __floats2half2_rn(v.x, v.y);
    }
    s_gw[tid] = gw[(size_t)n * 256 + tid];
    if (tid < 32) s_idx[tid] = conn[(size_t)n * KK + tid];

    const size_t off = ((size_t)b * NN + n) * DD;
    const float2 key = *(const float2*)&g_ek[off + 2 * l];
    __syncthreads();

    const __half2* pmb = (const __half2*)(pm_in + (size_t)b * NN * DD);
    u64 accp[4];

    // ---- prologue: gather chunk 0 (lane l holds d=2l,2l+1 as half2) ----
    __half2 m[8];
    #pragma unroll
    for (int kk = 0; kk < 8; kk++)
        m[kk] = __ldg(&pmb[s_idx[kk] * 32 + l]);

    #pragma unroll
    for (int c = 0; c < 4; c++) {
        // ---- phase 1: convert, sim partials, premul t = m*bw (m dies) ----
        float v[8];
        u64 t[8];
        #pragma unroll
        for (int kk = 0; kk < 8; kk++) {
            const float2 mf  = __half22float2(m[kk]);
            const float2 bwv = __half22float2(s_bwh[(c * 8 + kk) * 32 + l]);
            v[kk] = key.x * mf.x + key.y * mf.y;
            t[kk] = mul2(pk2(mf.x, mf.y), pk2(bwv.x, bwv.y));
        }

        // ---- phase 2: prefetch next chunk's gathers (overlaps 3-4) ----
        if (c < 3) {
            #pragma unroll
            for (int kk = 0; kk < 8; kk++)
                m[kk] = __ldg(&pmb[s_idx[(c + 1) * 8 + kk] * 32 + l]);
        }

        // ---- phase 3: butterfly multi-reduce (8 sums over 32 lanes) ----
        {
            const bool h16 = (l & 16);
            #pragma unroll
            for (int i = 0; i < 4; i++) {
                const float keep = h16 ? v[4 + i] : v[i];
                const float send = h16 ? v[i]     : v[4 + i];
                v[i] = keep + __shfl_xor_sync(0xffffffffu, send, 16);
            }
            const bool h8 = (l & 8);
            #pragma unroll
            for (int i = 0; i < 2; i++) {
                const float keep = h8 ? v[2 + i] : v[i];
                const float send = h8 ? v[i]     : v[2 + i];
                v[i] = keep + __shfl_xor_sync(0xffffffffu, send, 8);
            }
            const bool h4 = (l & 4);
            {
                const float keep = h4 ? v[1] : v[0];
                const float send = h4 ? v[0] : v[1];
                v[0] = keep + __shfl_xor_sync(0xffffffffu, send, 4);
            }
            v[0] += __shfl_xor_sync(0xffffffffu, v[0], 2);
            v[0] += __shfl_xor_sync(0xffffffffu, v[0], 1);
        }
        // lane l holds sim for kk = (l >> 2) & 7
        const float w = sigf(v[0]);

        // ---- phase 4: packed accumulate (chunk c == branch c) ----
        u64 a = 0ull;
        #pragma unroll
        for (int kk = 0; kk < 8; kk++) {
            const float wk = __shfl_sync(0xffffffffu, w, kk << 2);
            a = fma2(t[kk], pk2(wk, wk), a);
        }
        accp[c] = a;
    }

    // ---- branch tanh -> group sum -> group tanh (ng=1, mean = identity) ----
    float r0 = 0.f, r1 = 0.f;
    #pragma unroll
    for (int nb = 0; nb < 4; nb++) {
        const float2 av  = upk2(accp[nb]);
        const float2 gwv = *(const float2*)&s_gw[nb * 64 + 2 * l];
        r0 += tanhfast(av.x) * gwv.x;
        r1 += tanhfast(av.y) * gwv.y;
    }
    r0 = tanhfast(r0);
    r1 = tanhfast(r1);

    if (n < C_) {   // cc injection on first C neurons
        const float2 ccv = *(const float2*)&cc[(((size_t)b * T_ + t0) * C_ + n) * DD + 2 * l];
        r0 += ccv.x;
        r1 += ccv.y;
    }

    // ---- h / message update ----
    const float ed = g_ed[(size_t)b * NN + n];
    const float2 h = *(const float2*)&g_h[off + 2 * l];
    const float nh0 = ed * h.x + (1.f - ed) * r0;
    const float nh1 = ed * h.y + (1.f - ed) * r1;
    *(float2*)&g_h[off + 2 * l] = make_float2(nh0, nh1);
    const float2 ep = *(const float2*)&g_ep[off + 2 * l];
    const float p0 = tanhfast(nh0 * ep.x);
    const float p1 = tanhfast(nh1 * ep.y);
    *((__half2*)(pm_out + off) + l) = __floats2half2_rn(p0, p1);

    if (n < C_) {   // emit the 4 timesteps this update covers (fp32 output)
        #pragma unroll
        for (int tt = 0; tt < 4; tt++) {
            const size_t oo = (((size_t)b * T_ + t0 + tt) * C_ + n) * DD + 2 * l;
            *(float2*)&out[oo] = make_float2(p0, p1);
        }
    }
}

// =============================================================================
extern "C" void kernel_launch(void* const* d_in, const int* in_sizes, int n_in,
                              void* d_out, int out_size)
{
    const float* cc    = (const float*)d_in[0];
    const float* h_in  = (const float*)d_in[1];
    const float* pm_in = (const float*)d_in[2];
    const float* tp    = (const float*)d_in[3];
    const float* tk    = (const float*)d_in[4];
    const float* prim  = (const float*)d_in[5];
    const float* keyp  = (const float*)d_in[6];
    const float* dlog  = (const float*)d_in[7];
    const float* bw    = (const float*)d_in[8];
    const float* gw    = (const float*)d_in[9];
    const float* fc1w  = (const float*)d_in[10];
    const float* fc1b  = (const float*)d_in[11];
    const float* fc2w  = (const float*)d_in[12];
    const float* fc2b  = (const float*)d_in[13];
    const float* mll   = (const float*)d_in[14];
    const int*   conn  = (const int*)d_in[15];
    float* out = (float*)d_out;

    modk<<<NN, 512>>>(h_in, pm_in, tp, tk, prim, keyp, dlog,
                      fc1w, fc1b, fc2w, fc2b, mll);

    // stride = 4 (fixed by setup): updates at t = 0,4,...,28; output replicated x4
    for (int u = 0; u < 8; u++) {
        stepk<<<NN, 256>>>(u & 1, 4 * u, cc, bw, gw, conn, out);
    }
}